// round 2
// baseline (speedup 1.0000x reference)
#include <cuda_runtime.h>
#include <math.h>

#define Bb   8
#define Dd   160
#define Nn   32768
#define Kk   589
#define Rr   8
#define NT   256
#define NBLK 128                 // Nn / NT
#define XSS  260                 // x-tile smem row stride (words): 16B-aligned, conflict-free pass2
#define CTS  260
#define EPSV 1e-6f
#define DN   ((size_t)Dd * (size_t)Nn)

// ---------------- static device scratch (no allocation allowed) ----------------
__device__ float g_E    [Dd * Kk];                 // estimators [D][K]
__device__ float g_bases[Bb * Kk * Rr];
__device__ float g_t1   [Bb * Kk * Rr];            // bases @ ctc
__device__ float g_Eb   [Bb * Dd * Rr];            // E @ bases
__device__ float g_t2   [Bb * Dd * Rr];            // E @ t1
__device__ float g_G    [Bb * 64];                 // Eb^T Eb
__device__ float g_coef [(size_t)Bb * Nn * Rr];    // 8.4 MB
__device__ float g_sxc  [(size_t)Bb * NBLK * Dd * Rr]; // x@coef partials, 5.24 MB
__device__ float g_sctc [Bb * NBLK * 64];          // ctc partials
__device__ float g_xcoef[Bb * Dd * Rr];            // reduced x@coef

// ---------------- packed f32x2 helpers ----------------
__device__ __forceinline__ unsigned long long pk2(float lo, float hi) {
    unsigned long long r;
    asm("mov.b64 %0, {%1, %2};" : "=l"(r) : "f"(lo), "f"(hi));
    return r;
}
__device__ __forceinline__ void upk2(unsigned long long v, float& lo, float& hi) {
    asm("mov.b64 {%0, %1}, %2;" : "=f"(lo), "=f"(hi) : "l"(v));
}
__device__ __forceinline__ unsigned long long fma2_(unsigned long long a,
                                                    unsigned long long b,
                                                    unsigned long long c) {
    unsigned long long d;
    asm("fma.rn.f32x2 %0, %1, %2, %3;" : "=l"(d) : "l"(a), "l"(b), "l"(c));
    return d;
}

// ---------------- build RBF estimator bank ----------------
__global__ void k_build_E() {
    int d = blockIdx.x;
    for (int k = threadIdx.x; k < Kk; k += blockDim.x) {
        float v;
        if (k == 588) {
            v = 1.0f;
        } else {
            float sig; int n;
            if      (k < 160) { sig = 6.0f;  n = k; }
            else if (k < 320) { sig = 8.0f;  n = k - 160; }
            else if (k < 400) { sig = 12.0f; n = (k - 320) * 2; }
            else if (k < 480) { sig = 15.0f; n = (k - 400) * 2; }
            else if (k < 534) { sig = 18.0f; n = (k - 480) * 3; }
            else              { sig = 24.0f; n = (k - 534) * 3; }
            float diff = (float)d - (float)n;
            v = expf(-0.5f * (diff * diff) / (2.0f * sig * sig));
        }
        g_E[d * Kk + k] = v;
    }
}

// ---------------- L2-normalize bases_init over K per (b,r) ----------------
__global__ void k_norm(const float* __restrict__ bin) {
    int b = blockIdx.x;
    int r = threadIdx.x >> 5;
    int l = threadIdx.x & 31;
    float ss = 0.f;
    for (int k = l; k < Kk; k += 32) {
        float v = bin[(b * Kk + k) * Rr + r];
        ss += v * v;
    }
    #pragma unroll
    for (int o = 16; o; o >>= 1) ss += __shfl_xor_sync(0xffffffffu, ss, o);
    float nrm = fmaxf(sqrtf(ss), 1e-12f);
    for (int k = l; k < Kk; k += 32)
        g_bases[(b * Kk + k) * Rr + r] = bin[(b * Kk + k) * Rr + r] / nrm;
}

// ---------------- dst = E @ src (src [K,R], dst [D,R]). MODE0: bases->Eb, MODE1: t1->t2 ----
template<int MODE>
__global__ void k_EbG() {
    __shared__ __align__(16) float sb[Kk * Rr];
    int b = blockIdx.y;
    const float* src = MODE ? g_t1 : g_bases;
    float* dst       = MODE ? g_t2 : g_Eb;
    for (int i = threadIdx.x; i < Kk * Rr; i += 256) sb[i] = src[b * Kk * Rr + i];
    __syncthreads();
    int idx = blockIdx.x * 256 + threadIdx.x;     // 0..1279
    int d = idx >> 3, r = idx & 7;
    const float* Er = g_E + d * Kk;
    float acc = 0.f;
    #pragma unroll 4
    for (int k = 0; k < Kk; k++) acc = fmaf(Er[k], sb[k * Rr + r], acc);
    dst[(b * Dd + d) * Rr + r] = acc;
}

// ---------------- G = Eb^T Eb ----------------
__global__ void k_G() {
    int b = blockIdx.x, t = threadIdx.x;          // 64 threads
    int r = t >> 3, s = t & 7;
    const float* eb = g_Eb + b * Dd * Rr;
    float acc = 0.f;
    #pragma unroll 4
    for (int d = 0; d < Dd; d++) acc = fmaf(eb[d * 8 + r], eb[d * 8 + s], acc);
    g_G[b * 64 + t] = acc;
}

// ---------------- fused big pass: num_c -> coef update -> x@coef + ctc partials ----------------
template<int INIT>
__global__ __launch_bounds__(NT) void k_pass(const float* __restrict__ x) {
    extern __shared__ float sm[];
    float* xs  = sm;                      // [Dd][XSS]
    float* ct  = xs + Dd * XSS;           // [Rr][CTS] coef_new transposed
    float* ebs = ct + Rr * CTS;           // [Dd][Rr]
    float* gs  = ebs + Dd * Rr;           // [64]

    int t = threadIdx.x;
    int blk = blockIdx.x, b = blockIdx.y;
    int n0 = blk * NT;
    const float* xb = x + (size_t)b * DN + n0 + t;

    for (int i = t; i < Dd * Rr; i += NT) ebs[i] = g_Eb[b * Dd * Rr + i];
    if (t < 64) gs[t] = g_G[b * 64 + t];
    __syncthreads();

    // pass 1: stage x tile + L[r] = sum_d x[d][n]*Eb[d][r]
    unsigned long long L2a[4] = {0ull, 0ull, 0ull, 0ull};
    #pragma unroll 8
    for (int d = 0; d < Dd; d++) {
        float xv = __ldg(xb + (size_t)d * Nn);
        xs[d * XSS + t] = xv;
        unsigned long long x2 = pk2(xv, xv);
        const ulonglong2* ep = (const ulonglong2*)(ebs + d * 8);
        ulonglong2 e0 = ep[0], e1 = ep[1];
        L2a[0] = fma2_(x2, e0.x, L2a[0]);
        L2a[1] = fma2_(x2, e0.y, L2a[1]);
        L2a[2] = fma2_(x2, e1.x, L2a[2]);
        L2a[3] = fma2_(x2, e1.y, L2a[3]);
    }
    float L[8];
    upk2(L2a[0], L[0], L[1]); upk2(L2a[1], L[2], L[3]);
    upk2(L2a[2], L[4], L[5]); upk2(L2a[3], L[6], L[7]);

    int n = n0 + t;
    float c_old[8];
    if (INIT) {
        float m = L[0];
        #pragma unroll
        for (int i = 1; i < 8; i++) m = fmaxf(m, L[i]);
        float ps = 0.f;
        #pragma unroll
        for (int i = 0; i < 8; i++) { c_old[i] = expf(L[i] - m); ps += c_old[i]; }
        float inv = 1.0f / ps;
        #pragma unroll
        for (int i = 0; i < 8; i++) c_old[i] *= inv;
    } else {
        const float4* cg = (const float4*)(g_coef + ((size_t)b * Nn + n) * 8);
        float4 a = cg[0], c = cg[1];
        c_old[0]=a.x; c_old[1]=a.y; c_old[2]=a.z; c_old[3]=a.w;
        c_old[4]=c.x; c_old[5]=c.y; c_old[6]=c.z; c_old[7]=c.w;
    }

    // coef update: c1[r] = c_old[r]*L[r] / (sum_s c_old[s]*G[s][r] + eps)
    float c1[8];
    #pragma unroll
    for (int r = 0; r < 8; r++) {
        float den = 0.f;
        #pragma unroll
        for (int s = 0; s < 8; s++) den = fmaf(c_old[s], gs[s * 8 + r], den);
        c1[r] = c_old[r] * L[r] / (den + EPSV);
    }

    float4* cgw = (float4*)(g_coef + ((size_t)b * Nn + n) * 8);
    cgw[0] = make_float4(c1[0], c1[1], c1[2], c1[3]);
    cgw[1] = make_float4(c1[4], c1[5], c1[6], c1[7]);
    #pragma unroll
    for (int r = 0; r < 8; r++) ct[r * CTS + t] = c1[r];
    __syncthreads();

    // pass 2: xcoef partials acc[d][r] = sum_n xs[d][n]*c1[n][r]
    {
        int r  = t & 7;
        int db = t >> 3;                   // 0..31
        unsigned long long acc2[5] = {0ull, 0ull, 0ull, 0ull, 0ull};
        #pragma unroll 2
        for (int n4 = 0; n4 < NT / 4; n4++) {
            ulonglong2 cc = *(const ulonglong2*)(ct + r * CTS + n4 * 4);
            #pragma unroll
            for (int j = 0; j < 5; j++) {
                ulonglong2 xx = *(const ulonglong2*)(xs + (db + 32 * j) * XSS + n4 * 4);
                acc2[j] = fma2_(xx.x, cc.x, acc2[j]);
                acc2[j] = fma2_(xx.y, cc.y, acc2[j]);
            }
        }
        float* outp = g_sxc + (size_t)(b * NBLK + blk) * (Dd * Rr);
        #pragma unroll
        for (int j = 0; j < 5; j++) {
            float lo, hi; upk2(acc2[j], lo, hi);
            outp[j * 256 + t] = lo + hi;   // index == d*8+r
        }
    }

    // pass 2b: ctc block partials (threads 0..63)
    if (t < 64) {
        int r = t >> 3, s = t & 7;
        float acc = 0.f;
        #pragma unroll 4
        for (int i = 0; i < NT / 2; i++) {
            float2 a = *(const float2*)(ct + r * CTS + 2 * i);
            float2 bq = *(const float2*)(ct + s * CTS + 2 * i);
            acc = fmaf(a.x, bq.x, acc);
            acc = fmaf(a.y, bq.y, acc);
        }
        g_sctc[(size_t)(b * NBLK + blk) * 64 + t] = acc;
    }
}

// ---------------- reduce x@coef partials ----------------
__global__ void k_reduce_xc() {
    int j = blockIdx.x, b = blockIdx.y, t = threadIdx.x;
    int o = j * 256 + t;                            // 0..1279
    const float* p = g_sxc + (size_t)b * NBLK * (Dd * Rr) + o;
    float acc = 0.f;
    #pragma unroll 8
    for (int blk = 0; blk < NBLK; blk++) acc += p[(size_t)blk * (Dd * Rr)];
    g_xcoef[b * (Dd * Rr) + o] = acc;
}

// ---------------- reduce ctc + t1 = bases @ ctc ----------------
__global__ void k_bctc() {
    __shared__ float sc[64];
    int b = blockIdx.x, t = threadIdx.x;            // 64 threads
    float acc = 0.f;
    const float* p = g_sctc + (size_t)b * NBLK * 64 + t;
    #pragma unroll 8
    for (int blk = 0; blk < NBLK; blk++) acc += p[blk * 64];
    sc[t] = acc;
    __syncthreads();
    const float* bs = g_bases + b * Kk * Rr;
    float* t1 = g_t1 + b * Kk * Rr;
    for (int idx = t; idx < Kk * Rr; idx += 64) {
        int k = idx >> 3, r = idx & 7;
        float a = 0.f;
        #pragma unroll
        for (int s = 0; s < 8; s++) a = fmaf(bs[k * 8 + s], sc[s * 8 + r], a);
        t1[idx] = a;
    }
}

// ---------------- bases *= (E^T xcoef) / (E^T t2 + eps) ----------------
__global__ void k_basesupd() {
    __shared__ float sx[Dd * Rr];
    __shared__ float st[Dd * Rr];
    int b = blockIdx.y, t = threadIdx.x;
    for (int i = t; i < Dd * Rr; i += 256) {
        sx[i] = g_xcoef[b * Dd * Rr + i];
        st[i] = g_t2[b * Dd * Rr + i];
    }
    __syncthreads();
    int idx = blockIdx.x * 256 + t;
    if (idx >= Kk * Rr) return;
    int k = idx >> 3, r = idx & 7;
    float num = 0.f, den = 0.f;
    #pragma unroll 4
    for (int d = 0; d < Dd; d++) {
        float e = g_E[d * Kk + k];
        num = fmaf(e, sx[d * 8 + r], num);
        den = fmaf(e, st[d * 8 + r], den);
    }
    g_bases[b * Kk * Rr + idx] *= num / (den + EPSV);
}

// ---------------- final coef update + reconstruction ----------------
__global__ __launch_bounds__(NT) void k_final(const float* __restrict__ x,
                                              float* __restrict__ out) {
    __shared__ __align__(16) float ebs[Dd * Rr];
    __shared__ float gs[64];
    int t = threadIdx.x, blk = blockIdx.x, b = blockIdx.y;
    int n0 = blk * NT;
    for (int i = t; i < Dd * Rr; i += NT) ebs[i] = g_Eb[b * Dd * Rr + i];
    if (t < 64) gs[t] = g_G[b * 64 + t];
    __syncthreads();

    const float* xb = x + (size_t)b * DN + n0 + t;
    unsigned long long L2a[4] = {0ull, 0ull, 0ull, 0ull};
    #pragma unroll 8
    for (int d = 0; d < Dd; d++) {
        float xv = __ldg(xb + (size_t)d * Nn);
        unsigned long long x2 = pk2(xv, xv);
        const ulonglong2* ep = (const ulonglong2*)(ebs + d * 8);
        ulonglong2 e0 = ep[0], e1 = ep[1];
        L2a[0] = fma2_(x2, e0.x, L2a[0]);
        L2a[1] = fma2_(x2, e0.y, L2a[1]);
        L2a[2] = fma2_(x2, e1.x, L2a[2]);
        L2a[3] = fma2_(x2, e1.y, L2a[3]);
    }
    float L[8];
    upk2(L2a[0], L[0], L[1]); upk2(L2a[1], L[2], L[3]);
    upk2(L2a[2], L[4], L[5]); upk2(L2a[3], L[6], L[7]);

    int n = n0 + t;
    const float4* cg = (const float4*)(g_coef + ((size_t)b * Nn + n) * 8);
    float4 a = cg[0], c = cg[1];
    float c_old[8] = {a.x, a.y, a.z, a.w, c.x, c.y, c.z, c.w};

    float c1[8];
    #pragma unroll
    for (int r = 0; r < 8; r++) {
        float den = 0.f;
        #pragma unroll
        for (int s = 0; s < 8; s++) den = fmaf(c_old[s], gs[s * 8 + r], den);
        c1[r] = c_old[r] * L[r] / (den + EPSV);
    }

    float* ob = out + (size_t)b * DN + n0 + t;
    #pragma unroll 4
    for (int d = 0; d < Dd; d++) {
        const float4* ep = (const float4*)(ebs + d * 8);
        float4 e0 = ep[0], e1 = ep[1];
        float v = e0.x * c1[0] + e0.y * c1[1] + e0.z * c1[2] + e0.w * c1[3]
                + e1.x * c1[4] + e1.y * c1[5] + e1.z * c1[6] + e1.w * c1[7];
        ob[(size_t)d * Nn] = v;
    }
}

// ---------------- launch ----------------
extern "C" void kernel_launch(void* const* d_in, const int* in_sizes, int n_in,
                              void* d_out, int out_size) {
    const float* x = (const float*)d_in[0];
    const float* binit = (const float*)d_in[1];
    float* out = (float*)d_out;

    const size_t PS = (size_t)(Dd * XSS + Rr * CTS + Dd * Rr + 64) * sizeof(float);
    cudaFuncSetAttribute(k_pass<1>, cudaFuncAttributeMaxDynamicSharedMemorySize, (int)PS);
    cudaFuncSetAttribute(k_pass<0>, cudaFuncAttributeMaxDynamicSharedMemorySize, (int)PS);

    k_build_E<<<Dd, 256>>>();
    k_norm<<<Bb, 256>>>(binit);

    for (int s = 0; s < 4; s++) {
        k_EbG<0><<<dim3(5, Bb), 256>>>();
        k_G<<<Bb, 64>>>();
        if (s == 0) k_pass<1><<<dim3(NBLK, Bb), NT, PS>>>(x);
        else        k_pass<0><<<dim3(NBLK, Bb), NT, PS>>>(x);
        k_reduce_xc<<<dim3(5, Bb), 256>>>();
        k_bctc<<<Bb, 64>>>();
        k_EbG<1><<<dim3(5, Bb), 256>>>();
        k_basesupd<<<dim3(19, Bb), 256>>>();
    }
    k_EbG<0><<<dim3(5, Bb), 256>>>();
    k_G<<<Bb, 64>>>();
    k_final<<<dim3(NBLK, Bb), NT>>>(x, out);
}

// round 3
// speedup vs baseline: 1.3589x; 1.3589x over previous
#include <cuda_runtime.h>
#include <math.h>

#define Bb   8
#define Dd   160
#define Nn   32768
#define Kk   589
#define KP   592                 // padded K stride (float4-aligned)
#define Rr   8
#define NT   256
#define NBLK 128                 // Nn / NT
#define XSS  260
#define CTS  260
#define EPSV 1e-6f
#define DN   ((size_t)Dd * (size_t)Nn)
#define KR   (Kk * Rr)           // 4712
#define DR   (Dd * Rr)           // 1280

// ---------------- static device scratch ----------------
__device__ float g_E    [Dd * KP];                 // [d][k] padded, pads = 0
__device__ float g_Et   [Kk * Dd];                 // [k][d]
__device__ float g_EtE  [(size_t)Kk * KP];         // [k][k'] padded, pads = 0
__device__ float g_bases[Bb * KR];
__device__ float g_t1   [Bb * KR];                 // bases @ ctc
__device__ float g_Eb   [Bb * DR];
__device__ float g_coef [(size_t)Bb * Nn * Rr];
__device__ float g_sxc  [(size_t)Bb * NBLK * DR];  // x@coef block partials
__device__ float g_sctc [Bb * NBLK * 64];          // ctc block partials
__device__ float g_xcoef[Bb * DR];

// ---------------- packed f32x2 helpers ----------------
__device__ __forceinline__ unsigned long long pk2(float lo, float hi) {
    unsigned long long r;
    asm("mov.b64 %0, {%1, %2};" : "=l"(r) : "f"(lo), "f"(hi));
    return r;
}
__device__ __forceinline__ void upk2(unsigned long long v, float& lo, float& hi) {
    asm("mov.b64 {%0, %1}, %2;" : "=f"(lo), "=f"(hi) : "l"(v));
}
__device__ __forceinline__ unsigned long long fma2_(unsigned long long a,
                                                    unsigned long long b,
                                                    unsigned long long c) {
    unsigned long long d;
    asm("fma.rn.f32x2 %0, %1, %2, %3;" : "=l"(d) : "l"(a), "l"(b), "l"(c));
    return d;
}

// ---------------- build RBF estimator bank (+ transpose) ----------------
__global__ void k_build_E() {
    int d = blockIdx.x;
    for (int k = threadIdx.x; k < KP; k += blockDim.x) {
        float v = 0.f;
        if (k < Kk) {
            if (k == 588) {
                v = 1.0f;
            } else {
                float sig; int n;
                if      (k < 160) { sig = 6.0f;  n = k; }
                else if (k < 320) { sig = 8.0f;  n = k - 160; }
                else if (k < 400) { sig = 12.0f; n = (k - 320) * 2; }
                else if (k < 480) { sig = 15.0f; n = (k - 400) * 2; }
                else if (k < 534) { sig = 18.0f; n = (k - 480) * 3; }
                else              { sig = 24.0f; n = (k - 534) * 3; }
                float diff = (float)d - (float)n;
                v = expf(-0.5f * (diff * diff) / (2.0f * sig * sig));
            }
        }
        g_E[d * KP + k] = v;
        if (k < Kk) g_Et[k * Dd + d] = v;
    }
}

// ---------------- EtE = E^T E (once per replay), tiled 8 rows/block ----------------
__global__ void k_EtE() {
    __shared__ float se[Dd * 8];                   // [d][i]
    int i0 = blockIdx.x * 8;
    int t = threadIdx.x;
    for (int idx = t; idx < Dd * 8; idx += 256) {
        int d = idx >> 3, i = idx & 7;
        int ki = i0 + i;
        se[idx] = (ki < Kk) ? g_Et[ki * Dd + d] : 0.f;
    }
    __syncthreads();
    for (int j = t; j < KP; j += 256) {
        float acc[8] = {0, 0, 0, 0, 0, 0, 0, 0};
        if (j < Kk) {
            #pragma unroll 4
            for (int d = 0; d < Dd; d++) {
                float e = g_E[d * KP + j];
                #pragma unroll
                for (int i = 0; i < 8; i++) acc[i] = fmaf(e, se[d * 8 + i], acc[i]);
            }
        }
        #pragma unroll
        for (int i = 0; i < 8; i++)
            if (i0 + i < Kk) g_EtE[(size_t)(i0 + i) * KP + j] = acc[i];
    }
}

// ---------------- L2-normalize bases_init over K per (b,r) ----------------
__global__ void k_norm(const float* __restrict__ bin) {
    int b = blockIdx.x;
    int r = threadIdx.x >> 5;
    int l = threadIdx.x & 31;
    float ss = 0.f;
    for (int k = l; k < Kk; k += 32) {
        float v = bin[(b * Kk + k) * Rr + r];
        ss += v * v;
    }
    #pragma unroll
    for (int o = 16; o; o >>= 1) ss += __shfl_xor_sync(0xffffffffu, ss, o);
    float nrm = fmaxf(sqrtf(ss), 1e-12f);
    for (int k = l; k < Kk; k += 32)
        g_bases[(b * Kk + k) * Rr + r] = bin[(b * Kk + k) * Rr + r] / nrm;
}

// ---------------- Eb = E @ bases : grid(5, B) ----------------
__global__ void k_EbG() {
    __shared__ __align__(16) float sb[KP * Rr];
    int b = blockIdx.y;
    for (int i = threadIdx.x; i < KP * Rr; i += 256)
        sb[i] = (i < KR) ? g_bases[b * KR + i] : 0.f;
    __syncthreads();
    int idx = blockIdx.x * 256 + threadIdx.x;      // 0..1279
    int d = idx >> 3, r = idx & 7;
    const float4* er = (const float4*)(g_E + d * KP);
    float acc = 0.f;
    #pragma unroll 4
    for (int i = 0; i < KP / 4; i++) {
        float4 e = er[i];
        acc = fmaf(e.x, sb[(4 * i + 0) * 8 + r], acc);
        acc = fmaf(e.y, sb[(4 * i + 1) * 8 + r], acc);
        acc = fmaf(e.z, sb[(4 * i + 2) * 8 + r], acc);
        acc = fmaf(e.w, sb[(4 * i + 3) * 8 + r], acc);
    }
    g_Eb[b * DR + idx] = acc;
}

// ---------------- fused big pass ----------------
template<int INIT>
__global__ __launch_bounds__(NT) void k_pass(const float* __restrict__ x) {
    extern __shared__ float sm[];
    float* xs  = sm;                      // [Dd][XSS]
    float* ct  = xs + Dd * XSS;           // [Rr][CTS]
    float* ebs = ct + Rr * CTS;           // [Dd][Rr]
    float* gs  = ebs + DR;                // [64]

    int t = threadIdx.x;
    int blk = blockIdx.x, b = blockIdx.y;
    int n0 = blk * NT;
    const float* xb = x + (size_t)b * DN + n0 + t;

    for (int i = t; i < DR; i += NT) ebs[i] = g_Eb[b * DR + i];
    __syncthreads();

    // in-block Gram G = Eb^T Eb (overlaps with others' LDG stalls)
    if (t < 64) {
        int r = t >> 3, s = t & 7;
        float a = 0.f;
        #pragma unroll 8
        for (int d = 0; d < Dd; d++) a = fmaf(ebs[d * 8 + r], ebs[d * 8 + s], a);
        gs[t] = a;
    }

    // pass 1: stage x tile + L[r] = sum_d x[d][n]*Eb[d][r], MLP-16 loads
    unsigned long long L2a[4] = {0ull, 0ull, 0ull, 0ull};
    #pragma unroll 1
    for (int d0 = 0; d0 < Dd; d0 += 16) {
        float xv[16];
        #pragma unroll
        for (int i = 0; i < 16; i++) xv[i] = __ldg(xb + (size_t)(d0 + i) * Nn);
        #pragma unroll
        for (int i = 0; i < 16; i++) {
            int d = d0 + i;
            xs[d * XSS + t] = xv[i];
            unsigned long long x2 = pk2(xv[i], xv[i]);
            const ulonglong2* ep = (const ulonglong2*)(ebs + d * 8);
            ulonglong2 e0 = ep[0], e1 = ep[1];
            L2a[0] = fma2_(x2, e0.x, L2a[0]);
            L2a[1] = fma2_(x2, e0.y, L2a[1]);
            L2a[2] = fma2_(x2, e1.x, L2a[2]);
            L2a[3] = fma2_(x2, e1.y, L2a[3]);
        }
    }
    __syncthreads();   // gs visible; xs complete

    float L[8];
    upk2(L2a[0], L[0], L[1]); upk2(L2a[1], L[2], L[3]);
    upk2(L2a[2], L[4], L[5]); upk2(L2a[3], L[6], L[7]);

    int n = n0 + t;
    float c_old[8];
    if (INIT) {
        float m = L[0];
        #pragma unroll
        for (int i = 1; i < 8; i++) m = fmaxf(m, L[i]);
        float ps = 0.f;
        #pragma unroll
        for (int i = 0; i < 8; i++) { c_old[i] = expf(L[i] - m); ps += c_old[i]; }
        float inv = 1.0f / ps;
        #pragma unroll
        for (int i = 0; i < 8; i++) c_old[i] *= inv;
    } else {
        const float4* cg = (const float4*)(g_coef + ((size_t)b * Nn + n) * 8);
        float4 a = cg[0], c = cg[1];
        c_old[0]=a.x; c_old[1]=a.y; c_old[2]=a.z; c_old[3]=a.w;
        c_old[4]=c.x; c_old[5]=c.y; c_old[6]=c.z; c_old[7]=c.w;
    }

    float c1[8];
    #pragma unroll
    for (int r = 0; r < 8; r++) {
        float den = 0.f;
        #pragma unroll
        for (int s = 0; s < 8; s++) den = fmaf(c_old[s], gs[s * 8 + r], den);
        c1[r] = c_old[r] * L[r] / (den + EPSV);
    }

    float4* cgw = (float4*)(g_coef + ((size_t)b * Nn + n) * 8);
    cgw[0] = make_float4(c1[0], c1[1], c1[2], c1[3]);
    cgw[1] = make_float4(c1[4], c1[5], c1[6], c1[7]);
    #pragma unroll
    for (int r = 0; r < 8; r++) ct[r * CTS + t] = c1[r];
    __syncthreads();

    // pass 2: xcoef partials
    {
        int r  = t & 7;
        int db = t >> 3;
        unsigned long long acc2[5] = {0ull, 0ull, 0ull, 0ull, 0ull};
        #pragma unroll 2
        for (int n4 = 0; n4 < NT / 4; n4++) {
            ulonglong2 cc = *(const ulonglong2*)(ct + r * CTS + n4 * 4);
            #pragma unroll
            for (int j = 0; j < 5; j++) {
                ulonglong2 xx = *(const ulonglong2*)(xs + (db + 32 * j) * XSS + n4 * 4);
                acc2[j] = fma2_(xx.x, cc.x, acc2[j]);
                acc2[j] = fma2_(xx.y, cc.y, acc2[j]);
            }
        }
        float* outp = g_sxc + (size_t)(b * NBLK + blk) * DR;
        #pragma unroll
        for (int j = 0; j < 5; j++) {
            float lo, hi; upk2(acc2[j], lo, hi);
            outp[j * 256 + t] = lo + hi;
        }
    }

    // pass 2b: ctc block partials
    if (t < 64) {
        int r = t >> 3, s = t & 7;
        float acc = 0.f;
        #pragma unroll 4
        for (int i = 0; i < NT / 2; i++) {
            float2 a = *(const float2*)(ct + r * CTS + 2 * i);
            float2 bq = *(const float2*)(ct + s * CTS + 2 * i);
            acc = fmaf(a.x, bq.x, acc);
            acc = fmaf(a.y, bq.y, acc);
        }
        g_sctc[(size_t)(b * NBLK + blk) * 64 + t] = acc;
    }
}

// ---------------- glue A: reduce x@coef, reduce ctc, t1 = bases @ ctc ----------------
__global__ void k_glueA() {
    __shared__ float sc[64];
    __shared__ float spart[256];
    int b = blockIdx.x, t = threadIdx.x;
    for (int o = t; o < DR; o += 256) {
        const float* p = g_sxc + (size_t)b * NBLK * DR + o;
        float a0 = 0, a1 = 0, a2 = 0, a3 = 0;
        #pragma unroll 4
        for (int blk = 0; blk < NBLK; blk += 4) {
            a0 += p[(size_t)(blk + 0) * DR];
            a1 += p[(size_t)(blk + 1) * DR];
            a2 += p[(size_t)(blk + 2) * DR];
            a3 += p[(size_t)(blk + 3) * DR];
        }
        g_xcoef[b * DR + o] = (a0 + a1) + (a2 + a3);
    }
    {
        int o = t & 63, q = t >> 6;
        const float* p = g_sctc + (size_t)b * NBLK * 64 + o;
        float acc = 0.f;
        #pragma unroll 4
        for (int blk = q * 32; blk < q * 32 + 32; blk++) acc += p[blk * 64];
        spart[t] = acc;
    }
    __syncthreads();
    if (t < 64) sc[t] = (spart[t] + spart[t + 64]) + (spart[t + 128] + spart[t + 192]);
    __syncthreads();
    const float* bs = g_bases + b * KR;
    float* t1 = g_t1 + b * KR;
    for (int idx = t; idx < KR; idx += 256) {
        int k = idx >> 3, r = idx & 7;
        float a = 0.f;
        #pragma unroll
        for (int s = 0; s < 8; s++) a = fmaf(bs[k * 8 + s], sc[s * 8 + r], a);
        t1[idx] = a;
    }
}

// ---------------- glue B: bases *= (E^T xcoef) / (EtE @ t1 + eps) ----------------
__global__ __launch_bounds__(256) void k_glueB() {
    __shared__ float sx[DR];
    __shared__ __align__(16) float st1[KP * Rr];
    int b = blockIdx.y, t = threadIdx.x;
    for (int i = t; i < DR; i += 256) sx[i] = g_xcoef[b * DR + i];
    for (int i = t; i < KP * Rr; i += 256) st1[i] = (i < KR) ? g_t1[b * KR + i] : 0.f;
    __syncthreads();
    int idx = blockIdx.x * 256 + t;
    if (idx >= KR) return;
    int k = idx >> 3, r = idx & 7;
    const float4* et = (const float4*)(g_Et + k * Dd);
    float num = 0.f;
    #pragma unroll 4
    for (int i = 0; i < Dd / 4; i++) {
        float4 e = et[i];
        num = fmaf(e.x, sx[(4 * i + 0) * 8 + r], num);
        num = fmaf(e.y, sx[(4 * i + 1) * 8 + r], num);
        num = fmaf(e.z, sx[(4 * i + 2) * 8 + r], num);
        num = fmaf(e.w, sx[(4 * i + 3) * 8 + r], num);
    }
    const float4* ee = (const float4*)(g_EtE + (size_t)k * KP);
    float den = 0.f;
    #pragma unroll 4
    for (int i = 0; i < KP / 4; i++) {
        float4 v = ee[i];
        den = fmaf(v.x, st1[(4 * i + 0) * 8 + r], den);
        den = fmaf(v.y, st1[(4 * i + 1) * 8 + r], den);
        den = fmaf(v.z, st1[(4 * i + 2) * 8 + r], den);
        den = fmaf(v.w, st1[(4 * i + 3) * 8 + r], den);
    }
    g_bases[b * KR + idx] *= num / (den + EPSV);
}

// ---------------- final coef update + reconstruction ----------------
__global__ __launch_bounds__(NT) void k_final(const float* __restrict__ x,
                                              float* __restrict__ out) {
    __shared__ __align__(16) float ebs[DR];
    __shared__ float gs[64];
    int t = threadIdx.x, blk = blockIdx.x, b = blockIdx.y;
    int n0 = blk * NT;
    for (int i = t; i < DR; i += NT) ebs[i] = g_Eb[b * DR + i];
    __syncthreads();
    if (t < 64) {
        int r = t >> 3, s = t & 7;
        float a = 0.f;
        #pragma unroll 8
        for (int d = 0; d < Dd; d++) a = fmaf(ebs[d * 8 + r], ebs[d * 8 + s], a);
        gs[t] = a;
    }

    const float* xb = x + (size_t)b * DN + n0 + t;
    unsigned long long L2a[4] = {0ull, 0ull, 0ull, 0ull};
    #pragma unroll 1
    for (int d0 = 0; d0 < Dd; d0 += 16) {
        float xv[16];
        #pragma unroll
        for (int i = 0; i < 16; i++) xv[i] = __ldg(xb + (size_t)(d0 + i) * Nn);
        #pragma unroll
        for (int i = 0; i < 16; i++) {
            unsigned long long x2 = pk2(xv[i], xv[i]);
            const ulonglong2* ep = (const ulonglong2*)(ebs + (d0 + i) * 8);
            ulonglong2 e0 = ep[0], e1 = ep[1];
            L2a[0] = fma2_(x2, e0.x, L2a[0]);
            L2a[1] = fma2_(x2, e0.y, L2a[1]);
            L2a[2] = fma2_(x2, e1.x, L2a[2]);
            L2a[3] = fma2_(x2, e1.y, L2a[3]);
        }
    }
    __syncthreads();  // gs visible

    float L[8];
    upk2(L2a[0], L[0], L[1]); upk2(L2a[1], L[2], L[3]);
    upk2(L2a[2], L[4], L[5]); upk2(L2a[3], L[6], L[7]);

    int n = n0 + t;
    const float4* cg = (const float4*)(g_coef + ((size_t)b * Nn + n) * 8);
    float4 a = cg[0], c = cg[1];
    float c_old[8] = {a.x, a.y, a.z, a.w, c.x, c.y, c.z, c.w};

    float c1[8];
    #pragma unroll
    for (int r = 0; r < 8; r++) {
        float den = 0.f;
        #pragma unroll
        for (int s = 0; s < 8; s++) den = fmaf(c_old[s], gs[s * 8 + r], den);
        c1[r] = c_old[r] * L[r] / (den + EPSV);
    }

    float* ob = out + (size_t)b * DN + n0 + t;
    #pragma unroll 4
    for (int d = 0; d < Dd; d++) {
        const float4* ep = (const float4*)(ebs + d * 8);
        float4 e0 = ep[0], e1 = ep[1];
        float v = e0.x * c1[0] + e0.y * c1[1] + e0.z * c1[2] + e0.w * c1[3]
                + e1.x * c1[4] + e1.y * c1[5] + e1.z * c1[6] + e1.w * c1[7];
        ob[(size_t)d * Nn] = v;
    }
}

// ---------------- launch ----------------
extern "C" void kernel_launch(void* const* d_in, const int* in_sizes, int n_in,
                              void* d_out, int out_size) {
    const float* x = (const float*)d_in[0];
    const float* binit = (const float*)d_in[1];
    float* out = (float*)d_out;

    const int PS = (Dd * XSS + Rr * CTS + DR + 64) * (int)sizeof(float);
    cudaFuncSetAttribute(k_pass<1>, cudaFuncAttributeMaxDynamicSharedMemorySize, PS);
    cudaFuncSetAttribute(k_pass<0>, cudaFuncAttributeMaxDynamicSharedMemorySize, PS);

    k_build_E<<<Dd, 256>>>();
    k_EtE<<<74, 256>>>();
    k_norm<<<Bb, 256>>>(binit);
    k_EbG<<<dim3(5, Bb), 256>>>();

    for (int s = 0; s < 4; s++) {
        if (s == 0) k_pass<1><<<dim3(NBLK, Bb), NT, PS>>>(x);
        else        k_pass<0><<<dim3(NBLK, Bb), NT, PS>>>(x);
        k_glueA<<<Bb, 256>>>();
        k_glueB<<<dim3(19, Bb), 256>>>();
        k_EbG<<<dim3(5, Bb), 256>>>();
    }
    k_final<<<dim3(NBLK, Bb), NT>>>(x, out);
}

// round 4
// speedup vs baseline: 1.5460x; 1.1377x over previous
#include <cuda_runtime.h>
#include <math.h>

#define Bb   8
#define Dd   160
#define Nn   32768
#define Kk   589
#define KP   592                 // padded K stride (float4-aligned)
#define Rr   8
#define NT   128                 // big-pass tile width (columns)
#define NBLK 256                 // Nn / NT
#define XSS  132                 // x-tile smem row stride
#define CTS  132
#define EPSV 1e-6f
#define DN   ((size_t)Dd * (size_t)Nn)
#define KR   (Kk * Rr)           // 4712
#define DR   (Dd * Rr)           // 1280
#define NTF  256                 // final-pass tile
#define NBLKF 128

// ---------------- static device scratch ----------------
__device__ float g_E    [Dd * KP];
__device__ float g_Et   [Kk * Dd];
__device__ float g_EtE  [(size_t)Kk * KP];
__device__ float g_bases[Bb * KR];
__device__ float g_t1   [Bb * KR];
__device__ float g_Eb   [Bb * DR];
__device__ float g_coef [(size_t)Bb * Nn * Rr];
__device__ float g_sxc  [(size_t)Bb * NBLK * DR];   // 10.5 MB
__device__ float g_sctc [Bb * NBLK * 64];
__device__ float g_xcoef[Bb * DR];

// ---------------- packed f32x2 helpers ----------------
__device__ __forceinline__ unsigned long long pk2(float lo, float hi) {
    unsigned long long r;
    asm("mov.b64 %0, {%1, %2};" : "=l"(r) : "f"(lo), "f"(hi));
    return r;
}
__device__ __forceinline__ void upk2(unsigned long long v, float& lo, float& hi) {
    asm("mov.b64 {%0, %1}, %2;" : "=f"(lo), "=f"(hi) : "l"(v));
}
__device__ __forceinline__ unsigned long long fma2_(unsigned long long a,
                                                    unsigned long long b,
                                                    unsigned long long c) {
    unsigned long long d;
    asm("fma.rn.f32x2 %0, %1, %2, %3;" : "=l"(d) : "l"(a), "l"(b), "l"(c));
    return d;
}

// ---------------- build RBF estimator bank (+ transpose) ----------------
__global__ void k_build_E() {
    int d = blockIdx.x;
    for (int k = threadIdx.x; k < KP; k += blockDim.x) {
        float v = 0.f;
        if (k < Kk) {
            if (k == 588) {
                v = 1.0f;
            } else {
                float sig; int n;
                if      (k < 160) { sig = 6.0f;  n = k; }
                else if (k < 320) { sig = 8.0f;  n = k - 160; }
                else if (k < 400) { sig = 12.0f; n = (k - 320) * 2; }
                else if (k < 480) { sig = 15.0f; n = (k - 400) * 2; }
                else if (k < 534) { sig = 18.0f; n = (k - 480) * 3; }
                else              { sig = 24.0f; n = (k - 534) * 3; }
                float diff = (float)d - (float)n;
                v = expf(-0.5f * (diff * diff) / (2.0f * sig * sig));
            }
        }
        g_E[d * KP + k] = v;
        if (k < Kk) g_Et[k * Dd + d] = v;
    }
}

// ---------------- EtE = E^T E ----------------
__global__ void k_EtE() {
    __shared__ float se[Dd * 8];
    int i0 = blockIdx.x * 8;
    int t = threadIdx.x;
    for (int idx = t; idx < Dd * 8; idx += 256) {
        int d = idx >> 3, i = idx & 7;
        int ki = i0 + i;
        se[idx] = (ki < Kk) ? g_Et[ki * Dd + d] : 0.f;
    }
    __syncthreads();
    for (int j = t; j < KP; j += 256) {
        float acc[8] = {0, 0, 0, 0, 0, 0, 0, 0};
        if (j < Kk) {
            #pragma unroll 4
            for (int d = 0; d < Dd; d++) {
                float e = g_E[d * KP + j];
                #pragma unroll
                for (int i = 0; i < 8; i++) acc[i] = fmaf(e, se[d * 8 + i], acc[i]);
            }
        }
        #pragma unroll
        for (int i = 0; i < 8; i++)
            if (i0 + i < Kk) g_EtE[(size_t)(i0 + i) * KP + j] = acc[i];
    }
}

// ---------------- L2-normalize bases_init ----------------
__global__ void k_norm(const float* __restrict__ bin) {
    int b = blockIdx.x;
    int r = threadIdx.x >> 5;
    int l = threadIdx.x & 31;
    float ss = 0.f;
    for (int k = l; k < Kk; k += 32) {
        float v = bin[(b * Kk + k) * Rr + r];
        ss += v * v;
    }
    #pragma unroll
    for (int o = 16; o; o >>= 1) ss += __shfl_xor_sync(0xffffffffu, ss, o);
    float nrm = fmaxf(sqrtf(ss), 1e-12f);
    for (int k = l; k < Kk; k += 32)
        g_bases[(b * Kk + k) * Rr + r] = bin[(b * Kk + k) * Rr + r] / nrm;
}

// ---------------- Eb = E @ bases : grid(5, B), 4 accumulators ----------------
__global__ void k_EbG() {
    __shared__ __align__(16) float sb[KP * Rr];
    int b = blockIdx.y;
    for (int i = threadIdx.x; i < KP * Rr; i += 256)
        sb[i] = (i < KR) ? g_bases[b * KR + i] : 0.f;
    __syncthreads();
    int idx = blockIdx.x * 256 + threadIdx.x;
    int d = idx >> 3, r = idx & 7;
    const float4* er = (const float4*)(g_E + d * KP);
    float a0 = 0.f, a1 = 0.f, a2 = 0.f, a3 = 0.f;
    #pragma unroll 8
    for (int i = 0; i < KP / 4; i++) {
        float4 e = er[i];
        a0 = fmaf(e.x, sb[(4 * i + 0) * 8 + r], a0);
        a1 = fmaf(e.y, sb[(4 * i + 1) * 8 + r], a1);
        a2 = fmaf(e.z, sb[(4 * i + 2) * 8 + r], a2);
        a3 = fmaf(e.w, sb[(4 * i + 3) * 8 + r], a3);
    }
    g_Eb[b * DR + idx] = (a0 + a1) + (a2 + a3);
}

// ---------------- fused big pass (NT=128, 2 CTAs/SM) ----------------
template<int INIT>
__global__ __launch_bounds__(NT) void k_pass(const float* __restrict__ x) {
    extern __shared__ float sm[];
    float* xs  = sm;                      // [Dd][XSS]
    float* ct  = xs + Dd * XSS;           // [Rr][CTS]
    float* ebs = ct + Rr * CTS;           // [DR]
    float* gs  = ebs + DR;                // [64]

    int t = threadIdx.x;
    int blk = blockIdx.x, b = blockIdx.y;
    int n0 = blk * NT;
    const float* xb = x + (size_t)b * DN + n0 + t;

    for (int i = t; i < DR; i += NT) ebs[i] = g_Eb[b * DR + i];
    __syncthreads();

    // in-block Gram (overlaps with LDG stalls of other warps)
    if (t < 64) {
        int r = t >> 3, s = t & 7;
        float a = 0.f;
        #pragma unroll 8
        for (int d = 0; d < Dd; d++) a = fmaf(ebs[d * 8 + r], ebs[d * 8 + s], a);
        gs[t] = a;
    }

    // pass 1: stage tile + L[r] = sum_d x[d][n]*Eb[d][r], MLP-16
    unsigned long long L2a[4] = {0ull, 0ull, 0ull, 0ull};
    #pragma unroll 1
    for (int d0 = 0; d0 < Dd; d0 += 16) {
        float xv[16];
        #pragma unroll
        for (int i = 0; i < 16; i++) xv[i] = __ldg(xb + (size_t)(d0 + i) * Nn);
        #pragma unroll
        for (int i = 0; i < 16; i++) {
            int d = d0 + i;
            xs[d * XSS + t] = xv[i];
            unsigned long long x2 = pk2(xv[i], xv[i]);
            const ulonglong2* ep = (const ulonglong2*)(ebs + d * 8);
            ulonglong2 e0 = ep[0], e1 = ep[1];
            L2a[0] = fma2_(x2, e0.x, L2a[0]);
            L2a[1] = fma2_(x2, e0.y, L2a[1]);
            L2a[2] = fma2_(x2, e1.x, L2a[2]);
            L2a[3] = fma2_(x2, e1.y, L2a[3]);
        }
    }
    __syncthreads();

    float L[8];
    upk2(L2a[0], L[0], L[1]); upk2(L2a[1], L[2], L[3]);
    upk2(L2a[2], L[4], L[5]); upk2(L2a[3], L[6], L[7]);

    int n = n0 + t;
    float c_old[8];
    if (INIT) {
        float m = L[0];
        #pragma unroll
        for (int i = 1; i < 8; i++) m = fmaxf(m, L[i]);
        float ps = 0.f;
        #pragma unroll
        for (int i = 0; i < 8; i++) { c_old[i] = expf(L[i] - m); ps += c_old[i]; }
        float inv = 1.0f / ps;
        #pragma unroll
        for (int i = 0; i < 8; i++) c_old[i] *= inv;
    } else {
        const float4* cg = (const float4*)(g_coef + ((size_t)b * Nn + n) * 8);
        float4 a = cg[0], c = cg[1];
        c_old[0]=a.x; c_old[1]=a.y; c_old[2]=a.z; c_old[3]=a.w;
        c_old[4]=c.x; c_old[5]=c.y; c_old[6]=c.z; c_old[7]=c.w;
    }

    float c1[8];
    #pragma unroll
    for (int r = 0; r < 8; r++) {
        float den = 0.f;
        #pragma unroll
        for (int s = 0; s < 8; s++) den = fmaf(c_old[s], gs[s * 8 + r], den);
        c1[r] = c_old[r] * L[r] / (den + EPSV);
    }

    float4* cgw = (float4*)(g_coef + ((size_t)b * Nn + n) * 8);
    cgw[0] = make_float4(c1[0], c1[1], c1[2], c1[3]);
    cgw[1] = make_float4(c1[4], c1[5], c1[6], c1[7]);
    #pragma unroll
    for (int r = 0; r < 8; r++) ct[r * CTS + t] = c1[r];
    __syncthreads();

    // pass 2: xcoef partials acc[d][r] = sum_n xs[d][n]*c1[n][r]
    {
        int r  = t & 7;
        int db = t >> 3;                  // 0..15
        unsigned long long acc2[10];
        #pragma unroll
        for (int j = 0; j < 10; j++) acc2[j] = 0ull;
        #pragma unroll 2
        for (int n4 = 0; n4 < NT / 4; n4++) {
            ulonglong2 cc = *(const ulonglong2*)(ct + r * CTS + n4 * 4);
            #pragma unroll
            for (int j = 0; j < 10; j++) {
                ulonglong2 xx = *(const ulonglong2*)(xs + (db + 16 * j) * XSS + n4 * 4);
                acc2[j] = fma2_(xx.x, cc.x, acc2[j]);
                acc2[j] = fma2_(xx.y, cc.y, acc2[j]);
            }
        }
        float* outp = g_sxc + (size_t)(b * NBLK + blk) * DR;
        #pragma unroll
        for (int j = 0; j < 10; j++) {
            float lo, hi; upk2(acc2[j], lo, hi);
            outp[j * 128 + t] = lo + hi;          // index == d*8+r
        }
    }

    // pass 2b: ctc block partials
    if (t < 64) {
        int r = t >> 3, s = t & 7;
        float acc = 0.f;
        #pragma unroll 4
        for (int i = 0; i < NT / 2; i++) {
            float2 a = *(const float2*)(ct + r * CTS + 2 * i);
            float2 bq = *(const float2*)(ct + s * CTS + 2 * i);
            acc = fmaf(a.x, bq.x, acc);
            acc = fmaf(a.y, bq.y, acc);
        }
        g_sctc[(size_t)(b * NBLK + blk) * 64 + t] = acc;
    }
}

// ---------------- glue A: grid(6,B). bx<5: reduce x@coef; bx==5: ctc + t1 ----------------
__global__ void k_glueA() {
    __shared__ float sc[64];
    __shared__ float spart[256];
    int bx = blockIdx.x, b = blockIdx.y, t = threadIdx.x;
    if (bx < 5) {
        int o = bx * 256 + t;                         // 0..1279
        const float* p = g_sxc + (size_t)b * NBLK * DR + o;
        float a0 = 0, a1 = 0, a2 = 0, a3 = 0;
        #pragma unroll 2
        for (int blk = 0; blk < NBLK; blk += 4) {
            a0 += p[(size_t)(blk + 0) * DR];
            a1 += p[(size_t)(blk + 1) * DR];
            a2 += p[(size_t)(blk + 2) * DR];
            a3 += p[(size_t)(blk + 3) * DR];
        }
        g_xcoef[b * DR + o] = (a0 + a1) + (a2 + a3);
        return;
    }
    {
        int o = t & 63, q = t >> 6;                   // 4 groups of 64 partials
        const float* p = g_sctc + (size_t)b * NBLK * 64 + o;
        float acc = 0.f;
        #pragma unroll 4
        for (int blk = q * 64; blk < q * 64 + 64; blk++) acc += p[blk * 64];
        spart[t] = acc;
    }
    __syncthreads();
    if (t < 64) sc[t] = (spart[t] + spart[t + 64]) + (spart[t + 128] + spart[t + 192]);
    __syncthreads();
    const float* bs = g_bases + b * KR;
    float* t1 = g_t1 + b * KR;
    for (int idx = t; idx < KR; idx += 256) {
        int k = idx >> 3, r = idx & 7;
        float a = 0.f;
        #pragma unroll
        for (int s = 0; s < 8; s++) a = fmaf(bs[k * 8 + s], sc[s * 8 + r], a);
        t1[idx] = a;
    }
}

// ---------------- glue B: bases *= (E^T xcoef) / (EtE @ t1 + eps) ----------------
__global__ __launch_bounds__(256) void k_glueB() {
    __shared__ float sx[DR];
    __shared__ __align__(16) float st1[KP * Rr];
    int b = blockIdx.y, t = threadIdx.x;
    for (int i = t; i < DR; i += 256) sx[i] = g_xcoef[b * DR + i];
    for (int i = t; i < KP * Rr; i += 256) st1[i] = (i < KR) ? g_t1[b * KR + i] : 0.f;
    __syncthreads();
    int idx = blockIdx.x * 256 + t;
    if (idx >= KR) return;
    int k = idx >> 3, r = idx & 7;
    const float4* et = (const float4*)(g_Et + k * Dd);
    float n0 = 0.f, n1 = 0.f, n2 = 0.f, n3 = 0.f;
    #pragma unroll 8
    for (int i = 0; i < Dd / 4; i++) {
        float4 e = et[i];
        n0 = fmaf(e.x, sx[(4 * i + 0) * 8 + r], n0);
        n1 = fmaf(e.y, sx[(4 * i + 1) * 8 + r], n1);
        n2 = fmaf(e.z, sx[(4 * i + 2) * 8 + r], n2);
        n3 = fmaf(e.w, sx[(4 * i + 3) * 8 + r], n3);
    }
    float num = (n0 + n1) + (n2 + n3);
    const float4* ee = (const float4*)(g_EtE + (size_t)k * KP);
    float d0 = 0.f, d1 = 0.f, d2 = 0.f, d3 = 0.f;
    #pragma unroll 8
    for (int i = 0; i < KP / 4; i++) {
        float4 v = ee[i];
        d0 = fmaf(v.x, st1[(4 * i + 0) * 8 + r], d0);
        d1 = fmaf(v.y, st1[(4 * i + 1) * 8 + r], d1);
        d2 = fmaf(v.z, st1[(4 * i + 2) * 8 + r], d2);
        d3 = fmaf(v.w, st1[(4 * i + 3) * 8 + r], d3);
    }
    float den = (d0 + d1) + (d2 + d3);
    g_bases[b * KR + idx] *= num / (den + EPSV);
}

// ---------------- final coef update + reconstruction ----------------
__global__ __launch_bounds__(NTF) void k_final(const float* __restrict__ x,
                                               float* __restrict__ out) {
    __shared__ __align__(16) float ebs[DR];
    __shared__ float gs[64];
    int t = threadIdx.x, blk = blockIdx.x, b = blockIdx.y;
    int n0 = blk * NTF;
    for (int i = t; i < DR; i += NTF) ebs[i] = g_Eb[b * DR + i];
    __syncthreads();
    if (t < 64) {
        int r = t >> 3, s = t & 7;
        float a = 0.f;
        #pragma unroll 8
        for (int d = 0; d < Dd; d++) a = fmaf(ebs[d * 8 + r], ebs[d * 8 + s], a);
        gs[t] = a;
    }

    const float* xb = x + (size_t)b * DN + n0 + t;
    unsigned long long L2a[4] = {0ull, 0ull, 0ull, 0ull};
    #pragma unroll 1
    for (int d0 = 0; d0 < Dd; d0 += 16) {
        float xv[16];
        #pragma unroll
        for (int i = 0; i < 16; i++) xv[i] = __ldg(xb + (size_t)(d0 + i) * Nn);
        #pragma unroll
        for (int i = 0; i < 16; i++) {
            unsigned long long x2 = pk2(xv[i], xv[i]);
            const ulonglong2* ep = (const ulonglong2*)(ebs + (d0 + i) * 8);
            ulonglong2 e0 = ep[0], e1 = ep[1];
            L2a[0] = fma2_(x2, e0.x, L2a[0]);
            L2a[1] = fma2_(x2, e0.y, L2a[1]);
            L2a[2] = fma2_(x2, e1.x, L2a[2]);
            L2a[3] = fma2_(x2, e1.y, L2a[3]);
        }
    }
    __syncthreads();

    float L[8];
    upk2(L2a[0], L[0], L[1]); upk2(L2a[1], L[2], L[3]);
    upk2(L2a[2], L[4], L[5]); upk2(L2a[3], L[6], L[7]);

    int n = n0 + t;
    const float4* cg = (const float4*)(g_coef + ((size_t)b * Nn + n) * 8);
    float4 a = cg[0], c = cg[1];
    float c_old[8] = {a.x, a.y, a.z, a.w, c.x, c.y, c.z, c.w};

    float c1[8];
    #pragma unroll
    for (int r = 0; r < 8; r++) {
        float den = 0.f;
        #pragma unroll
        for (int s = 0; s < 8; s++) den = fmaf(c_old[s], gs[s * 8 + r], den);
        c1[r] = c_old[r] * L[r] / (den + EPSV);
    }

    float* ob = out + (size_t)b * DN + n0 + t;
    #pragma unroll 4
    for (int d = 0; d < Dd; d++) {
        const float4* ep = (const float4*)(ebs + d * 8);
        float4 e0 = ep[0], e1 = ep[1];
        float v = e0.x * c1[0] + e0.y * c1[1] + e0.z * c1[2] + e0.w * c1[3]
                + e1.x * c1[4] + e1.y * c1[5] + e1.z * c1[6] + e1.w * c1[7];
        ob[(size_t)d * Nn] = v;
    }
}

// ---------------- launch ----------------
extern "C" void kernel_launch(void* const* d_in, const int* in_sizes, int n_in,
                              void* d_out, int out_size) {
    const float* x = (const float*)d_in[0];
    const float* binit = (const float*)d_in[1];
    float* out = (float*)d_out;

    const int PS = (Dd * XSS + Rr * CTS + DR + 64) * (int)sizeof(float);
    cudaFuncSetAttribute(k_pass<1>, cudaFuncAttributeMaxDynamicSharedMemorySize, PS);
    cudaFuncSetAttribute(k_pass<0>, cudaFuncAttributeMaxDynamicSharedMemorySize, PS);

    k_build_E<<<Dd, 256>>>();
    k_EtE<<<74, 256>>>();
    k_norm<<<Bb, 256>>>(binit);
    k_EbG<<<dim3(5, Bb), 256>>>();

    for (int s = 0; s < 4; s++) {
        if (s == 0) k_pass<1><<<dim3(NBLK, Bb), NT, PS>>>(x);
        else        k_pass<0><<<dim3(NBLK, Bb), NT, PS>>>(x);
        k_glueA<<<dim3(6, Bb), 256>>>();
        k_glueB<<<dim3(19, Bb), 256>>>();
        k_EbG<<<dim3(5, Bb), 256>>>();
    }
    k_final<<<dim3(NBLKF, Bb), NTF>>>(x, out);
}

// round 5
// speedup vs baseline: 1.7580x; 1.1371x over previous
#include <cuda_runtime.h>
#include <math.h>

#define Bb   8
#define Dd   160
#define Nn   32768
#define Kk   589
#define KP   592                 // padded K (float4-aligned, pads are zero)
#define KPR  (KP * 8)            // padded bases/t1 batch stride
#define Rr   8
#define NT   128                 // big-pass tile width
#define NBLK 256                 // Nn / NT
#define XSS  132                 // x-tile smem row stride (words)
#define CTS  132                 // cpk row stride (ull entries)
#define EPSV 1e-6f
#define DN   ((size_t)Dd * (size_t)Nn)
#define KR   (Kk * Rr)           // 4712
#define DR   (Dd * Rr)           // 1280
#define NTF  256
#define NBLKF 128

// ---------------- static device scratch ----------------
__device__ float g_E    [Dd * KP];
__device__ float g_Et   [Kk * Dd];
__device__ float g_EtE  [(size_t)Kk * KP];
__device__ float g_bases[Bb * KPR];
__device__ float g_t1   [Bb * KPR];
__device__ float g_ebp  [2 * Bb * DR];              // Eb split-K partials
__device__ float g_coef [(size_t)Bb * Nn * Rr];
__device__ float g_sxc  [(size_t)Bb * NBLK * DR];
__device__ float g_sctc [Bb * NBLK * 64];
__device__ float g_xcoef[Bb * DR];

// ---------------- packed f32x2 helpers ----------------
__device__ __forceinline__ unsigned long long pk2(float lo, float hi) {
    unsigned long long r;
    asm("mov.b64 %0, {%1, %2};" : "=l"(r) : "f"(lo), "f"(hi));
    return r;
}
__device__ __forceinline__ void upk2(unsigned long long v, float& lo, float& hi) {
    asm("mov.b64 {%0, %1}, %2;" : "=f"(lo), "=f"(hi) : "l"(v));
}
__device__ __forceinline__ unsigned long long fma2_(unsigned long long a,
                                                    unsigned long long b,
                                                    unsigned long long c) {
    unsigned long long d;
    asm("fma.rn.f32x2 %0, %1, %2, %3;" : "=l"(d) : "l"(a), "l"(b), "l"(c));
    return d;
}

// ---------------- build RBF estimator bank (+ transpose) ----------------
__global__ void k_build_E() {
    int d = blockIdx.x;
    for (int k = threadIdx.x; k < KP; k += blockDim.x) {
        float v = 0.f;
        if (k < Kk) {
            if (k == 588) {
                v = 1.0f;
            } else {
                float sig; int n;
                if      (k < 160) { sig = 6.0f;  n = k; }
                else if (k < 320) { sig = 8.0f;  n = k - 160; }
                else if (k < 400) { sig = 12.0f; n = (k - 320) * 2; }
                else if (k < 480) { sig = 15.0f; n = (k - 400) * 2; }
                else if (k < 534) { sig = 18.0f; n = (k - 480) * 3; }
                else              { sig = 24.0f; n = (k - 534) * 3; }
                float diff = (float)d - (float)n;
                v = expf(-0.5f * (diff * diff) / (2.0f * sig * sig));
            }
        }
        g_E[d * KP + k] = v;
        if (k < Kk) g_Et[k * Dd + d] = v;
    }
}

// ---------------- EtE = E^T E : grid(148), 4 rows/block, all cols ----------------
__global__ __launch_bounds__(256) void k_EtE() {
    __shared__ float se[Dd * 4];
    int i0 = blockIdx.x * 4;
    int t = threadIdx.x;
    for (int idx = t; idx < Dd * 4; idx += 256) {
        int d = idx >> 2, i = idx & 3;
        int ki = i0 + i;
        se[idx] = (ki < Kk) ? g_Et[ki * Dd + d] : 0.f;
    }
    __syncthreads();
    int j0 = t, j1 = t + 256, j2 = t + 512;
    bool has2 = (j2 < KP);
    float a0[4] = {0,0,0,0}, a1[4] = {0,0,0,0}, a2[4] = {0,0,0,0};
    #pragma unroll 4
    for (int d = 0; d < Dd; d++) {
        float e0 = g_E[d * KP + j0];
        float e1 = g_E[d * KP + j1];
        float e2 = has2 ? g_E[d * KP + j2] : 0.f;
        #pragma unroll
        for (int i = 0; i < 4; i++) {
            float s = se[d * 4 + i];
            a0[i] = fmaf(e0, s, a0[i]);
            a1[i] = fmaf(e1, s, a1[i]);
            a2[i] = fmaf(e2, s, a2[i]);
        }
    }
    #pragma unroll
    for (int i = 0; i < 4; i++) {
        int row = i0 + i;
        if (row < Kk) {
            g_EtE[(size_t)row * KP + j0] = a0[i];
            g_EtE[(size_t)row * KP + j1] = a1[i];
            if (has2) g_EtE[(size_t)row * KP + j2] = a2[i];
        }
    }
}

// ---------------- L2-normalize bases_init (+ zero pads) ----------------
__global__ void k_norm(const float* __restrict__ bin) {
    int b = blockIdx.x;
    int r = threadIdx.x >> 5;
    int l = threadIdx.x & 31;
    float ss = 0.f;
    for (int k = l; k < Kk; k += 32) {
        float v = bin[(b * Kk + k) * Rr + r];
        ss += v * v;
    }
    #pragma unroll
    for (int o = 16; o; o >>= 1) ss += __shfl_xor_sync(0xffffffffu, ss, o);
    float nrm = fmaxf(sqrtf(ss), 1e-12f);
    for (int k = l; k < Kk; k += 32)
        g_bases[b * KPR + k * Rr + r] = bin[(b * Kk + k) * Rr + r] / nrm;
    if (threadIdx.x < KPR - KR)
        g_bases[b * KPR + KR + threadIdx.x] = 0.f;
}

// ---------------- Eb partials: grid(40, 2, Bb), 8 lanes per output ----------------
__global__ __launch_bounds__(256) void k_EbG2() {
    int t = threadIdx.x;
    int q = blockIdx.y, b = blockIdx.z;
    int out = t >> 3, kg = t & 7;
    int idx = blockIdx.x * 32 + out;               // 0..1279
    int d = idx >> 3, r = idx & 7;
    const float* Erow = g_E + d * KP + q * 296 + kg;
    const float* brow = g_bases + b * KPR + (q * 296 + kg) * 8 + r;
    float acc0 = 0.f, acc1 = 0.f;
    #pragma unroll
    for (int i = 0; i < 36; i += 2) {
        acc0 = fmaf(Erow[8 * i],       brow[64 * i],        acc0);
        acc1 = fmaf(Erow[8 * (i + 1)], brow[64 * (i + 1)],  acc1);
    }
    acc0 = fmaf(Erow[8 * 36], brow[64 * 36], acc0);
    float acc = acc0 + acc1;
    acc += __shfl_down_sync(0xffffffffu, acc, 4);
    acc += __shfl_down_sync(0xffffffffu, acc, 2);
    acc += __shfl_down_sync(0xffffffffu, acc, 1);
    if (kg == 0) g_ebp[(q * Bb + b) * DR + idx] = acc;
}

// ---------------- fused big pass (NT=128, 2 CTAs/SM) ----------------
template<int INIT>
__global__ __launch_bounds__(NT) void k_pass(const float* __restrict__ x) {
    extern __shared__ float sm[];
    float* xs = sm;                                           // [160][132]
    unsigned long long* cpk = (unsigned long long*)(sm + Dd * XSS);  // [4][CTS] ull
    float* ebs = sm + Dd * XSS + 4 * CTS * 2;                 // [1280]
    float* gs  = ebs + DR;                                    // [64]

    int t = threadIdx.x;
    int blk = blockIdx.x, b = blockIdx.y;
    int n0 = blk * NT;
    const float* xb = x + (size_t)b * DN + n0 + t;

    for (int i = t; i < DR; i += NT)
        ebs[i] = g_ebp[b * DR + i] + g_ebp[(Bb + b) * DR + i];
    __syncthreads();

    if (t < 64) {
        int r = t >> 3, s = t & 7;
        float a = 0.f;
        #pragma unroll 8
        for (int d = 0; d < Dd; d++) a = fmaf(ebs[d * 8 + r], ebs[d * 8 + s], a);
        gs[t] = a;
    }

    // pass 1: stage tile + L[r] = sum_d x[d][n]*Eb[d][r]
    unsigned long long L2a[4] = {0ull, 0ull, 0ull, 0ull};
    #pragma unroll 1
    for (int d0 = 0; d0 < Dd; d0 += 16) {
        float xv[16];
        #pragma unroll
        for (int i = 0; i < 16; i++) xv[i] = __ldg(xb + (size_t)(d0 + i) * Nn);
        #pragma unroll
        for (int i = 0; i < 16; i++) {
            int d = d0 + i;
            xs[d * XSS + t] = xv[i];
            unsigned long long x2 = pk2(xv[i], xv[i]);
            const ulonglong2* ep = (const ulonglong2*)(ebs + d * 8);
            ulonglong2 e0 = ep[0], e1 = ep[1];
            L2a[0] = fma2_(x2, e0.x, L2a[0]);
            L2a[1] = fma2_(x2, e0.y, L2a[1]);
            L2a[2] = fma2_(x2, e1.x, L2a[2]);
            L2a[3] = fma2_(x2, e1.y, L2a[3]);
        }
    }
    __syncthreads();

    float L[8];
    upk2(L2a[0], L[0], L[1]); upk2(L2a[1], L[2], L[3]);
    upk2(L2a[2], L[4], L[5]); upk2(L2a[3], L[6], L[7]);

    int n = n0 + t;
    float c_old[8];
    if (INIT) {
        float m = L[0];
        #pragma unroll
        for (int i = 1; i < 8; i++) m = fmaxf(m, L[i]);
        float ps = 0.f;
        #pragma unroll
        for (int i = 0; i < 8; i++) { c_old[i] = expf(L[i] - m); ps += c_old[i]; }
        float inv = 1.0f / ps;
        #pragma unroll
        for (int i = 0; i < 8; i++) c_old[i] *= inv;
    } else {
        const float4* cg = (const float4*)(g_coef + ((size_t)b * Nn + n) * 8);
        float4 a = cg[0], c = cg[1];
        c_old[0]=a.x; c_old[1]=a.y; c_old[2]=a.z; c_old[3]=a.w;
        c_old[4]=c.x; c_old[5]=c.y; c_old[6]=c.z; c_old[7]=c.w;
    }

    float c1[8];
    #pragma unroll
    for (int r = 0; r < 8; r++) {
        float den = 0.f;
        #pragma unroll
        for (int s = 0; s < 8; s++) den = fmaf(c_old[s], gs[s * 8 + r], den);
        c1[r] = c_old[r] * L[r] / (den + EPSV);
    }

    float4* cgw = (float4*)(g_coef + ((size_t)b * Nn + n) * 8);
    cgw[0] = make_float4(c1[0], c1[1], c1[2], c1[3]);
    cgw[1] = make_float4(c1[4], c1[5], c1[6], c1[7]);
    #pragma unroll
    for (int p = 0; p < 4; p++)
        cpk[p * CTS + t] = pk2(c1[2 * p], c1[2 * p + 1]);
    __syncthreads();

    // pass 2: xcoef partials — thread = (r-pair p, d-base db); 5 d's each
    {
        int p  = t & 3;
        int db = t >> 2;                 // 0..31
        unsigned long long acc2[5] = {0ull, 0ull, 0ull, 0ull, 0ull};
        #pragma unroll 2
        for (int n4 = 0; n4 < NT / 4; n4++) {
            ulonglong2 ca = *(const ulonglong2*)(cpk + p * CTS + n4 * 4);
            ulonglong2 cb = *(const ulonglong2*)(cpk + p * CTS + n4 * 4 + 2);
            #pragma unroll
            for (int j = 0; j < 5; j++) {
                float4 xv = *(const float4*)(xs + (db + 32 * j) * XSS + n4 * 4);
                acc2[j] = fma2_(pk2(xv.x, xv.x), ca.x, acc2[j]);
                acc2[j] = fma2_(pk2(xv.y, xv.y), ca.y, acc2[j]);
                acc2[j] = fma2_(pk2(xv.z, xv.z), cb.x, acc2[j]);
                acc2[j] = fma2_(pk2(xv.w, xv.w), cb.y, acc2[j]);
            }
        }
        float* outp = g_sxc + (size_t)(b * NBLK + blk) * DR;
        #pragma unroll
        for (int j = 0; j < 5; j++) {
            float lo, hi; upk2(acc2[j], lo, hi);
            *(float2*)(outp + (db + 32 * j) * 8 + 2 * p) = make_float2(lo, hi);
        }
    }

    // pass 2b: ctc block partials (one warp)
    if (t < 32) {
        int r = t >> 2, sp = t & 3;
        int rp = r >> 1, rh = r & 1;
        unsigned long long a2 = 0ull;
        #pragma unroll 4
        for (int nn = 0; nn < NT; nn++) {
            float lo, hi; upk2(cpk[rp * CTS + nn], lo, hi);
            float crv = rh ? hi : lo;
            a2 = fma2_(pk2(crv, crv), cpk[sp * CTS + nn], a2);
        }
        float lo, hi; upk2(a2, lo, hi);
        *(float2*)(g_sctc + (size_t)(b * NBLK + blk) * 64 + r * 8 + 2 * sp) =
            make_float2(lo, hi);
    }
}

// ---------------- glue A: grid(6,B). bx<5: reduce x@coef; bx==5: ctc + t1 ----------------
__global__ void k_glueA() {
    __shared__ float sc[64];
    __shared__ float spart[256];
    int bx = blockIdx.x, b = blockIdx.y, t = threadIdx.x;
    if (bx < 5) {
        int o = bx * 256 + t;
        const float* p = g_sxc + (size_t)b * NBLK * DR + o;
        float a0 = 0, a1 = 0, a2 = 0, a3 = 0;
        #pragma unroll 2
        for (int blk = 0; blk < NBLK; blk += 4) {
            a0 += p[(size_t)(blk + 0) * DR];
            a1 += p[(size_t)(blk + 1) * DR];
            a2 += p[(size_t)(blk + 2) * DR];
            a3 += p[(size_t)(blk + 3) * DR];
        }
        g_xcoef[b * DR + o] = (a0 + a1) + (a2 + a3);
        return;
    }
    {
        int o = t & 63, q = t >> 6;
        const float* p = g_sctc + (size_t)b * NBLK * 64 + o;
        float acc = 0.f;
        #pragma unroll 4
        for (int blk = q * 64; blk < q * 64 + 64; blk++) acc += p[blk * 64];
        spart[t] = acc;
    }
    __syncthreads();
    if (t < 64) sc[t] = (spart[t] + spart[t + 64]) + (spart[t + 128] + spart[t + 192]);
    __syncthreads();
    const float* bs = g_bases + b * KPR;
    float* t1 = g_t1 + b * KPR;
    for (int idx = t; idx < KR; idx += 256) {
        int k = idx >> 3, r = idx & 7;
        float a = 0.f;
        #pragma unroll
        for (int s = 0; s < 8; s++) a = fmaf(bs[k * 8 + s], sc[s * 8 + r], a);
        t1[idx] = a;
    }
}

// ---------------- glue B: bases *= (E^T xcoef) / (EtE @ t1 + eps) ----------------
__global__ __launch_bounds__(256) void k_glueB() {
    __shared__ float sx[DR];
    __shared__ __align__(16) float st1[KP * Rr];
    int b = blockIdx.y, t = threadIdx.x;
    for (int i = t; i < DR; i += 256) sx[i] = g_xcoef[b * DR + i];
    for (int i = t; i < KP * Rr; i += 256) st1[i] = g_t1[b * KPR + i];
    __syncthreads();
    int idx = blockIdx.x * 256 + t;
    if (idx >= KR) return;
    int k = idx >> 3, r = idx & 7;
    const float4* et = (const float4*)(g_Et + k * Dd);
    float n0 = 0.f, n1 = 0.f, n2 = 0.f, n3 = 0.f;
    #pragma unroll 8
    for (int i = 0; i < Dd / 4; i++) {
        float4 e = et[i];
        n0 = fmaf(e.x, sx[(4 * i + 0) * 8 + r], n0);
        n1 = fmaf(e.y, sx[(4 * i + 1) * 8 + r], n1);
        n2 = fmaf(e.z, sx[(4 * i + 2) * 8 + r], n2);
        n3 = fmaf(e.w, sx[(4 * i + 3) * 8 + r], n3);
    }
    float num = (n0 + n1) + (n2 + n3);
    const float4* ee = (const float4*)(g_EtE + (size_t)k * KP);
    float d0 = 0.f, d1 = 0.f, d2 = 0.f, d3 = 0.f;
    #pragma unroll 8
    for (int i = 0; i < KP / 4; i++) {
        float4 v = ee[i];
        d0 = fmaf(v.x, st1[(4 * i + 0) * 8 + r], d0);
        d1 = fmaf(v.y, st1[(4 * i + 1) * 8 + r], d1);
        d2 = fmaf(v.z, st1[(4 * i + 2) * 8 + r], d2);
        d3 = fmaf(v.w, st1[(4 * i + 3) * 8 + r], d3);
    }
    float den = (d0 + d1) + (d2 + d3);
    g_bases[b * KPR + idx] *= num / (den + EPSV);
}

// ---------------- final coef update + reconstruction ----------------
__global__ __launch_bounds__(NTF) void k_final(const float* __restrict__ x,
                                               float* __restrict__ out) {
    __shared__ __align__(16) float ebs[DR];
    __shared__ float gs[64];
    int t = threadIdx.x, blk = blockIdx.x, b = blockIdx.y;
    int n0 = blk * NTF;
    for (int i = t; i < DR; i += NTF)
        ebs[i] = g_ebp[b * DR + i] + g_ebp[(Bb + b) * DR + i];
    __syncthreads();
    if (t < 64) {
        int r = t >> 3, s = t & 7;
        float a = 0.f;
        #pragma unroll 8
        for (int d = 0; d < Dd; d++) a = fmaf(ebs[d * 8 + r], ebs[d * 8 + s], a);
        gs[t] = a;
    }

    const float* xb = x + (size_t)b * DN + n0 + t;
    unsigned long long L2a[4] = {0ull, 0ull, 0ull, 0ull};
    #pragma unroll 1
    for (int d0 = 0; d0 < Dd; d0 += 16) {
        float xv[16];
        #pragma unroll
        for (int i = 0; i < 16; i++) xv[i] = __ldg(xb + (size_t)(d0 + i) * Nn);
        #pragma unroll
        for (int i = 0; i < 16; i++) {
            unsigned long long x2 = pk2(xv[i], xv[i]);
            const ulonglong2* ep = (const ulonglong2*)(ebs + (d0 + i) * 8);
            ulonglong2 e0 = ep[0], e1 = ep[1];
            L2a[0] = fma2_(x2, e0.x, L2a[0]);
            L2a[1] = fma2_(x2, e0.y, L2a[1]);
            L2a[2] = fma2_(x2, e1.x, L2a[2]);
            L2a[3] = fma2_(x2, e1.y, L2a[3]);
        }
    }
    __syncthreads();

    float L[8];
    upk2(L2a[0], L[0], L[1]); upk2(L2a[1], L[2], L[3]);
    upk2(L2a[2], L[4], L[5]); upk2(L2a[3], L[6], L[7]);

    int n = n0 + t;
    const float4* cg = (const float4*)(g_coef + ((size_t)b * Nn + n) * 8);
    float4 a = cg[0], c = cg[1];
    float c_old[8] = {a.x, a.y, a.z, a.w, c.x, c.y, c.z, c.w};

    float c1[8];
    #pragma unroll
    for (int r = 0; r < 8; r++) {
        float den = 0.f;
        #pragma unroll
        for (int s = 0; s < 8; s++) den = fmaf(c_old[s], gs[s * 8 + r], den);
        c1[r] = c_old[r] * L[r] / (den + EPSV);
    }

    float* ob = out + (size_t)b * DN + n0 + t;
    #pragma unroll 4
    for (int d = 0; d < Dd; d++) {
        const float4* ep = (const float4*)(ebs + d * 8);
        float4 e0 = ep[0], e1 = ep[1];
        float v = e0.x * c1[0] + e0.y * c1[1] + e0.z * c1[2] + e0.w * c1[3]
                + e1.x * c1[4] + e1.y * c1[5] + e1.z * c1[6] + e1.w * c1[7];
        ob[(size_t)d * Nn] = v;
    }
}

// ---------------- launch ----------------
extern "C" void kernel_launch(void* const* d_in, const int* in_sizes, int n_in,
                              void* d_out, int out_size) {
    const float* x = (const float*)d_in[0];
    const float* binit = (const float*)d_in[1];
    float* out = (float*)d_out;

    const int PS = (Dd * XSS + 4 * CTS * 2 + DR + 64) * (int)sizeof(float);
    cudaFuncSetAttribute(k_pass<1>, cudaFuncAttributeMaxDynamicSharedMemorySize, PS);
    cudaFuncSetAttribute(k_pass<0>, cudaFuncAttributeMaxDynamicSharedMemorySize, PS);

    k_build_E<<<Dd, 256>>>();
    k_norm<<<Bb, 256>>>(binit);
    k_EtE<<<148, 256>>>();
    k_EbG2<<<dim3(40, 2, Bb), 256>>>();

    for (int s = 0; s < 4; s++) {
        if (s == 0) k_pass<1><<<dim3(NBLK, Bb), NT, PS>>>(x);
        else        k_pass<0><<<dim3(NBLK, Bb), NT, PS>>>(x);
        k_glueA<<<dim3(6, Bb), 256>>>();
        k_glueB<<<dim3(19, Bb), 256>>>();
        k_EbG2<<<dim3(40, 2, Bb), 256>>>();
    }
    k_final<<<dim3(NBLKF, Bb), NTF>>>(x, out);
}